// round 11
// baseline (speedup 1.0000x reference)
#include <cuda_runtime.h>
#include <math.h>

#define FD   128          // feature dim (x, edge_attr, u, out)
#define HS   256          // hidden size
#define INC  384          // concat input to fc1
#define BB   1024         // batch segments
#define EE_MAX 1600000
#define EPB  8192         // edges per block in sort pipeline
#define RPT  (EPB / 256)  // 32 edges per thread
#define NB_MAX ((EE_MAX + EPB - 1) / EPB + 2)

// ---------------- scratch (static device globals; no allocation) ------------
__device__ float g_agge[BB * FD];
__device__ float g_aggn[BB * FD];
__device__ int   g_ehist[BB];
__device__ int   g_estart[BB + 1];
__device__ int   g_eseg[EE_MAX];
__device__ int   g_perm[EE_MAX];
__device__ int   g_bhist[BB * NB_MAX];
__device__ float g_t1[BB * HS];
__device__ float g_zln[BB * HS];
__device__ float g_gi[BB * 3 * HS];
__device__ float g_gh[BB * 3 * HS];

__device__ __forceinline__ int lowerb(const int* a, int n, int v) {
    int lo = 0, hi = n;
    while (lo < hi) {
        int mid = (lo + hi) >> 1;
        if (a[mid] < v) lo = mid + 1; else hi = mid;
    }
    return lo;
}

// ---------------- GEMM core: C = A @ W^T (+bias | +=C) ------------------------
// Tile BM x 64, BK=16, THREADS = BM*4, 4x4 microtiles.
// MODE 0: A row-major [M,K]
// MODE 2: A = concat(u, g_aggn), each FD wide (K=256)
template <int MODE>
__device__ __forceinline__ float4 loadA(const float* __restrict__ A,
                                        int row, int k, int K) {
    if (MODE == 0) {
        return *(const float4*)(A + (size_t)row * K + k);
    } else {
        if (k < FD)          return *(const float4*)(A      + (size_t)row * FD + k);
        else                 return *(const float4*)(g_aggn + (size_t)row * FD + (k - FD));
    }
}

template <int BM, int MODE, bool ACC>
__device__ __forceinline__ void gemm_body(const float* __restrict__ A,
                                          const float* __restrict__ W,
                                          const float* __restrict__ bias,
                                          float* __restrict__ C,
                                          int K, int Wstride, int Nd,
                                          int bm, int bn) {
    constexpr int WL = 64 / BM;          // W float4 loads per thread
    __shared__ float As[16][BM];
    __shared__ float Ws[16][64];
    const int t = threadIdx.x;           // THREADS = BM*4
    const int tm = t >> 4, tn = t & 15;
    const int lm = t >> 2, lk = (t & 3) << 2;
    float c[4][4] = {};

    float4 av = loadA<MODE>(A, bm + lm, lk, K);
    float4 wv[WL];
#pragma unroll
    for (int p = 0; p < WL; p++)
        wv[p] = *(const float4*)(W + (size_t)(bn + lm + p * BM) * Wstride + lk);

    for (int k0 = 0;;) {
        __syncthreads();
        As[lk + 0][lm] = av.x; As[lk + 1][lm] = av.y;
        As[lk + 2][lm] = av.z; As[lk + 3][lm] = av.w;
#pragma unroll
        for (int p = 0; p < WL; p++) {
            Ws[lk + 0][lm + p * BM] = wv[p].x;
            Ws[lk + 1][lm + p * BM] = wv[p].y;
            Ws[lk + 2][lm + p * BM] = wv[p].z;
            Ws[lk + 3][lm + p * BM] = wv[p].w;
        }
        __syncthreads();
        k0 += 16;
        if (k0 < K) {
            av = loadA<MODE>(A, bm + lm, k0 + lk, K);
#pragma unroll
            for (int p = 0; p < WL; p++)
                wv[p] = *(const float4*)(W + (size_t)(bn + lm + p * BM) * Wstride + k0 + lk);
        }
#pragma unroll
        for (int kk = 0; kk < 16; kk++) {
            float4 a = *(const float4*)&As[kk][tm << 2];
            float4 w = *(const float4*)&Ws[kk][tn << 2];
            c[0][0] += a.x * w.x; c[0][1] += a.x * w.y; c[0][2] += a.x * w.z; c[0][3] += a.x * w.w;
            c[1][0] += a.y * w.x; c[1][1] += a.y * w.y; c[1][2] += a.y * w.z; c[1][3] += a.y * w.w;
            c[2][0] += a.z * w.x; c[2][1] += a.z * w.y; c[2][2] += a.z * w.z; c[2][3] += a.z * w.w;
            c[3][0] += a.w * w.x; c[3][1] += a.w * w.y; c[3][2] += a.w * w.z; c[3][3] += a.w * w.w;
        }
        if (k0 >= K) break;
    }

    const int col = bn + (tn << 2);
    float4 bi;
    if (!ACC) bi = *(const float4*)(bias + col);
#pragma unroll
    for (int i = 0; i < 4; i++) {
        int row = bm + (tm << 2) + i;
        float4 o;
        if (ACC) {
            float4 old = *(const float4*)(C + (size_t)row * Nd + col);
            o.x = c[i][0] + old.x; o.y = c[i][1] + old.y;
            o.z = c[i][2] + old.z; o.w = c[i][3] + old.w;
        } else {
            o.x = c[i][0] + bi.x; o.y = c[i][1] + bi.y;
            o.z = c[i][2] + bi.z; o.w = c[i][3] + bi.w;
        }
        *(float4*)(C + (size_t)row * Nd + col) = o;
    }
}

// ---------------- stage 1: eseg+histogram  ⊕  node scatter-mean --------------
__global__ __launch_bounds__(256) void k_eseg(const int* __restrict__ ei,
                                              const int* __restrict__ batch,
                                              const float* __restrict__ x,
                                              int E, int NB, int N) {
    if ((int)blockIdx.x >= NB) {
        __shared__ float red[8 * FD];
        __shared__ int   sb[2];
        const int b = blockIdx.x - NB;
        const int t = threadIdx.x;
        const int w = t >> 5, lane = t & 31;
        if (t == 0) {
            sb[0] = lowerb(batch, N, b);
            sb[1] = lowerb(batch, N, b + 1);
        }
        __syncthreads();
        const int ns = sb[0], ne = sb[1];
        float4 acn = make_float4(0.f, 0.f, 0.f, 0.f);
        int j = ns + w;
        for (; j + 24 < ne; j += 32) {
            float4 v0 = ((const float4*)(x + (size_t)(j + 0)  * FD))[lane];
            float4 v1 = ((const float4*)(x + (size_t)(j + 8)  * FD))[lane];
            float4 v2 = ((const float4*)(x + (size_t)(j + 16) * FD))[lane];
            float4 v3 = ((const float4*)(x + (size_t)(j + 24) * FD))[lane];
            acn.x += (v0.x + v1.x) + (v2.x + v3.x);
            acn.y += (v0.y + v1.y) + (v2.y + v3.y);
            acn.z += (v0.z + v1.z) + (v2.z + v3.z);
            acn.w += (v0.w + v1.w) + (v2.w + v3.w);
        }
        for (; j < ne; j += 8) {
            float4 v0 = ((const float4*)(x + (size_t)j * FD))[lane];
            acn.x += v0.x; acn.y += v0.y; acn.z += v0.z; acn.w += v0.w;
        }
        ((float4*)red)[w * 32 + lane] = acn;
        __syncthreads();
        if (t < FD) {
            float s2 = 0.f;
#pragma unroll
            for (int w2 = 0; w2 < 8; w2++) s2 += red[w2 * FD + t];
            int cnt = ne - ns;
            g_aggn[(size_t)b * FD + t] = s2 / (float)max(cnt, 1);
        }
        return;
    }

    __shared__ int sh[BB];
    for (int i = threadIdx.x; i < BB; i += blockDim.x) sh[i] = 0;
    __syncthreads();
    const int base = blockIdx.x * EPB;
#pragma unroll 8
    for (int r = 0; r < RPT; r++) {
        int e = base + r * 256 + threadIdx.x;
        if (e < E) {
            int s = batch[ei[e]];
            g_eseg[e] = s;
            atomicAdd(&sh[s], 1);
        }
    }
    __syncthreads();
    for (int i = threadIdx.x; i < BB; i += blockDim.x)
        g_bhist[i * NB + blockIdx.x] = sh[i];
}

// ---------------- stage 2a: per-segment exclusive scan over blocks ----------
__global__ __launch_bounds__(256) void k_colscan(int NB) {
    const int seg = blockIdx.x;
    int* col = g_bhist + (size_t)seg * NB;
    const int t = threadIdx.x, lane = t & 31, w = t >> 5;
    __shared__ int wsum[8];
    __shared__ int carry;
    if (t == 0) carry = 0;
    __syncthreads();
    for (int base = 0; base < NB; base += 256) {
        int idx = base + t;
        int v = (idx < NB) ? col[idx] : 0;
        int inc = v;
#pragma unroll
        for (int o = 1; o < 32; o <<= 1) {
            int u2 = __shfl_up_sync(0xffffffffu, inc, o);
            if (lane >= o) inc += u2;
        }
        if (lane == 31) wsum[w] = inc;
        __syncthreads();
        int woff = 0;
        if (w > 0) {
#pragma unroll
            for (int i = 0; i < 7; i++) if (i < w) woff += wsum[i];
        }
        int excl = inc - v + woff + carry;
        if (idx < NB) col[idx] = excl;
        __syncthreads();
        if (t == 255) carry = excl + v;
        __syncthreads();
    }
    if (t == 0) g_ehist[seg] = carry;
}

// ---------------- stage 2b: exclusive scan over 1024 segment totals ---------
__global__ void k_scan() {
    __shared__ int s[BB];
    int t = threadIdx.x;
    int myv = g_ehist[t];
    s[t] = myv;
    __syncthreads();
    for (int off = 1; off < BB; off <<= 1) {
        int v = (t >= off) ? s[t - off] : 0;
        __syncthreads();
        s[t] += v;
        __syncthreads();
    }
    g_estart[t] = s[t] - myv;
    if (t == BB - 1) g_estart[BB] = s[t];
}

// ---------------- stage 3: contention-free scatter (plain, low-reg) ----------
__global__ __launch_bounds__(256) void k_scatter2(int E, int NB) {
    __shared__ int cur[BB];
    const int blk = blockIdx.x;
    for (int sgi = threadIdx.x; sgi < BB; sgi += 256)
        cur[sgi] = g_estart[sgi] + g_bhist[(size_t)sgi * NB + blk];
    __syncthreads();
    const int base = blk * EPB;
#pragma unroll 8
    for (int r = 0; r < RPT; r++) {
        int e = base + r * 256 + threadIdx.x;
        if (e < E) {
            int sgi = g_eseg[e];
            int p = atomicAdd(&cur[sgi], 1);
            g_perm[p] = e;
        }
    }
}

// ---------------- stage 4: [gh GEMM | pre-fc1 GEMM] first, then edge mean ----
__global__ __launch_bounds__(256) void k_agg(const float* __restrict__ ea,
                                             const float* __restrict__ h,
                                             const float* __restrict__ whh,
                                             const float* __restrict__ bhh,
                                             const float* __restrict__ u,
                                             const float* __restrict__ fc1w,
                                             const float* __restrict__ fc1b) {
    if (blockIdx.x < 192) {
        // ----- gh = h @ whh^T + bhh (independent of sort/agg) -----
        int g = blockIdx.x;                // 16 M-tiles x 12 N-tiles
        gemm_body<64, 0, false>(h, whh, bhh, g_gh, HS, HS, 3 * HS,
                                (g & 15) * 64, (g >> 4) * 64);
        return;
    }
    if (blockIdx.x < 256) {
        // ----- pre-fc1: t1 = u@Wu^T + aggn@Wn^T + b  (K=256) -----
        int g = blockIdx.x - 192;          // 16 M-tiles x 4 N-tiles
        gemm_body<64, 2, false>(u, fc1w, fc1b, g_t1, 2 * FD, INC, HS,
                                (g & 15) * 64, (g >> 4) * 64);
        return;
    }

    __shared__ float red[8 * FD];
    const int b = blockIdx.x - 256;
    const int t = threadIdx.x;
    const int w = t >> 5, lane = t & 31;

    const int es = g_estart[b], ee = g_estart[b + 1];
    float4 acc = make_float4(0.f, 0.f, 0.f, 0.f);
    int i = es + w;
    for (; i + 24 < ee; i += 32) {
        int e0 = g_perm[i];
        int e1 = g_perm[i + 8];
        int e2 = g_perm[i + 16];
        int e3 = g_perm[i + 24];
        float4 v0 = ((const float4*)(ea + (size_t)e0 * FD))[lane];
        float4 v1 = ((const float4*)(ea + (size_t)e1 * FD))[lane];
        float4 v2 = ((const float4*)(ea + (size_t)e2 * FD))[lane];
        float4 v3 = ((const float4*)(ea + (size_t)e3 * FD))[lane];
        acc.x += (v0.x + v1.x) + (v2.x + v3.x);
        acc.y += (v0.y + v1.y) + (v2.y + v3.y);
        acc.z += (v0.z + v1.z) + (v2.z + v3.z);
        acc.w += (v0.w + v1.w) + (v2.w + v3.w);
    }
    for (; i < ee; i += 8) {
        int e0 = g_perm[i];
        float4 v0 = ((const float4*)(ea + (size_t)e0 * FD))[lane];
        acc.x += v0.x; acc.y += v0.y; acc.z += v0.z; acc.w += v0.w;
    }
    ((float4*)red)[w * 32 + lane] = acc;
    __syncthreads();
    if (t < FD) {
        float s2 = 0.f;
#pragma unroll
        for (int w2 = 0; w2 < 8; w2++) s2 += red[w2 * FD + t];
        int cnt = ee - es;
        g_agge[(size_t)b * FD + t] = s2 / (float)max(cnt, 1);
    }
}

// ---------------- post-fc1: t1 += agge @ We^T  (K=128, BM=32) -----------------
__global__ __launch_bounds__(128) void k_fc1post(const float* __restrict__ fc1w) {
    gemm_body<32, 0, true>(g_agge, fc1w + 2 * FD, nullptr, g_t1, FD, INC, HS,
                           blockIdx.x * 32, blockIdx.y * 64);
}

// ---------------- MLP tail kernels -------------------------------------------
__global__ __launch_bounds__(256) void k_gru_gi(const float* __restrict__ wih,
                                                const float* __restrict__ bih) {
    gemm_body<64, 0, false>(g_zln, wih, bih, g_gi, HS, HS, 3 * HS,
                            blockIdx.x * 64, blockIdx.y * 64);
}

__global__ __launch_bounds__(128) void k_fc2(const float* __restrict__ hnew,
                                             const float* __restrict__ w,
                                             const float* __restrict__ b,
                                             float* __restrict__ out) {
    gemm_body<32, 0, false>(hnew, w, b, out, HS, HS, FD,
                            blockIdx.x * 32, blockIdx.y * 64);
}

// ---------------- LayerNorm + ReLU ------------------------------------------
__global__ __launch_bounds__(256) void k_ln(const float* __restrict__ g,
                                            const float* __restrict__ be) {
    const int b = blockIdx.x, t = threadIdx.x;
    float v = g_t1[(size_t)b * HS + t];
    float s = v, q = v * v;
#pragma unroll
    for (int o = 16; o; o >>= 1) {
        s += __shfl_down_sync(0xffffffffu, s, o);
        q += __shfl_down_sync(0xffffffffu, q, o);
    }
    __shared__ float ssum[8], ssq[8];
    __shared__ float smu, srv;
    if ((t & 31) == 0) { ssum[t >> 5] = s; ssq[t >> 5] = q; }
    __syncthreads();
    if (t == 0) {
        float S = 0.f, Q = 0.f;
#pragma unroll
        for (int i = 0; i < 8; i++) { S += ssum[i]; Q += ssq[i]; }
        float mu = S / (float)HS;
        float var = Q / (float)HS - mu * mu;
        smu = mu;
        srv = rsqrtf(var + 1e-5f);
    }
    __syncthreads();
    float o = (v - smu) * srv * g[t] + be[t];
    g_zln[(size_t)b * HS + t] = fmaxf(o, 0.f);
}

// ---------------- GRU gate combine (float4 vectorized) ------------------------
__global__ void k_gate(const float* __restrict__ h, float* __restrict__ hnew) {
    int idx = blockIdx.x * 256 + threadIdx.x;   // BB*HS/4 items
    int b = idx >> 6;
    int j = (idx & 63) * 4;
    const float* gi = g_gi + (size_t)b * 3 * HS;
    const float* gh = g_gh + (size_t)b * 3 * HS;
    float4 gir = *(const float4*)(gi + j);
    float4 giz = *(const float4*)(gi + HS + j);
    float4 gin = *(const float4*)(gi + 2 * HS + j);
    float4 ghr = *(const float4*)(gh + j);
    float4 ghz = *(const float4*)(gh + HS + j);
    float4 ghn = *(const float4*)(gh + 2 * HS + j);
    float4 hv  = *(const float4*)(h + (size_t)b * HS + j);
    float4 o;
#define GATE1(cc) { \
    float r  = 1.f / (1.f + expf(-(gir.cc + ghr.cc))); \
    float zg = 1.f / (1.f + expf(-(giz.cc + ghz.cc))); \
    float n  = tanhf(gin.cc + r * ghn.cc); \
    o.cc = (1.f - zg) * n + zg * hv.cc; }
    GATE1(x) GATE1(y) GATE1(z) GATE1(w)
#undef GATE1
    *(float4*)(hnew + (size_t)b * HS + j) = o;
}

// ---------------- launch ----------------------------------------------------
extern "C" void kernel_launch(void* const* d_in, const int* in_sizes, int n_in,
                              void* d_out, int out_size) {
    const float* x     = (const float*)d_in[0];
    const int*   ei    = (const int*)d_in[1];
    const float* ea    = (const float*)d_in[2];
    const float* h     = (const float*)d_in[3];
    const float* u     = (const float*)d_in[4];
    const int*   batch = (const int*)d_in[5];
    const float* fc1w  = (const float*)d_in[6];
    const float* fc1b  = (const float*)d_in[7];
    const float* lng   = (const float*)d_in[8];
    const float* lnb   = (const float*)d_in[9];
    const float* wih   = (const float*)d_in[10];
    const float* whh   = (const float*)d_in[11];
    const float* bih   = (const float*)d_in[12];
    const float* bhh   = (const float*)d_in[13];
    const float* fc2w  = (const float*)d_in[14];
    const float* fc2b  = (const float*)d_in[15];

    const int N = in_sizes[0] / FD;
    const int E = in_sizes[2] / FD;
    const int NB = (E + EPB - 1) / EPB;

    float* out  = (float*)d_out;           // [BB, FD]
    float* hnew = out + (size_t)BB * FD;   // [BB, HS]

    // eseg/hist ⊕ node-mean
    k_eseg<<<NB + BB, 256>>>(ei, batch, x, E, NB, N);
    k_colscan<<<BB, 256>>>(NB);
    k_scan<<<1, BB>>>();
    k_scatter2<<<NB, 256>>>(E, NB);
    // gh GEMM + pre-fc1 GEMM first (finish inside agg's stream), then edge-mean
    k_agg<<<256 + BB, 256>>>(ea, h, whh, bhh, u, fc1w, fc1b);

    k_fc1post<<<dim3(BB / 32, HS / 64), 128>>>(fc1w);
    k_ln<<<BB, HS>>>(lng, lnb);
    k_gru_gi<<<dim3(BB / 64, (3 * HS) / 64), 256>>>(wih, bih);
    k_gate<<<(BB * HS / 4) / 256, 256>>>(h, hnew);
    k_fc2<<<dim3(BB / 32, FD / 64), 128>>>(hnew, fc2w, fc2b, out);
}

// round 12
// speedup vs baseline: 1.0445x; 1.0445x over previous
#include <cuda_runtime.h>
#include <math.h>

#define FD   128          // feature dim (x, edge_attr, u, out)
#define HS   256          // hidden size
#define INC  384          // concat input to fc1
#define BB   1024         // batch segments
#define EE_MAX 1600000
#define EPB  2048         // edges per block in sort pipeline (validated: occ-bound)
#define NB_MAX ((EE_MAX + EPB - 1) / EPB + 2)

// ---------------- scratch (static device globals; no allocation) ------------
__device__ float g_agge[BB * FD];
__device__ float g_aggn[BB * FD];
__device__ int   g_ehist[BB];
__device__ int   g_estart[BB + 1];
__device__ int   g_eseg[EE_MAX];
__device__ int   g_perm[EE_MAX];
__device__ int   g_bhist[BB * NB_MAX];
__device__ int   g_done;                 // colscan completion counter (reset by last block)
__device__ float g_t1[BB * HS];
__device__ float g_zln[BB * HS];
__device__ float g_gi[BB * 3 * HS];
__device__ float g_gh[BB * 3 * HS];

__device__ __forceinline__ int lowerb(const int* a, int n, int v) {
    int lo = 0, hi = n;
    while (lo < hi) {
        int mid = (lo + hi) >> 1;
        if (a[mid] < v) lo = mid + 1; else hi = mid;
    }
    return lo;
}

// ---------------- GEMM core: C = A @ W^T (+bias | +=C) ------------------------
// Tile BM x 64, BK=16, THREADS = BM*4, 4x4 microtiles.
// MODE 0: A row-major [M,K]
// MODE 2: A = concat(u, g_aggn), each FD wide (K=256)
template <int MODE>
__device__ __forceinline__ float4 loadA(const float* __restrict__ A,
                                        int row, int k, int K) {
    if (MODE == 0) {
        return *(const float4*)(A + (size_t)row * K + k);
    } else {
        if (k < FD)          return *(const float4*)(A      + (size_t)row * FD + k);
        else                 return *(const float4*)(g_aggn + (size_t)row * FD + (k - FD));
    }
}

template <int BM, int MODE, bool ACC>
__device__ __forceinline__ void gemm_body(const float* __restrict__ A,
                                          const float* __restrict__ W,
                                          const float* __restrict__ bias,
                                          float* __restrict__ C,
                                          int K, int Wstride, int Nd,
                                          int bm, int bn) {
    constexpr int WL = 64 / BM;          // W float4 loads per thread
    __shared__ float As[16][BM];
    __shared__ float Ws[16][64];
    const int t = threadIdx.x;           // THREADS = BM*4
    const int tm = t >> 4, tn = t & 15;
    const int lm = t >> 2, lk = (t & 3) << 2;
    float c[4][4] = {};

    float4 av = loadA<MODE>(A, bm + lm, lk, K);
    float4 wv[WL];
#pragma unroll
    for (int p = 0; p < WL; p++)
        wv[p] = *(const float4*)(W + (size_t)(bn + lm + p * BM) * Wstride + lk);

    for (int k0 = 0;;) {
        __syncthreads();
        As[lk + 0][lm] = av.x; As[lk + 1][lm] = av.y;
        As[lk + 2][lm] = av.z; As[lk + 3][lm] = av.w;
#pragma unroll
        for (int p = 0; p < WL; p++) {
            Ws[lk + 0][lm + p * BM] = wv[p].x;
            Ws[lk + 1][lm + p * BM] = wv[p].y;
            Ws[lk + 2][lm + p * BM] = wv[p].z;
            Ws[lk + 3][lm + p * BM] = wv[p].w;
        }
        __syncthreads();
        k0 += 16;
        if (k0 < K) {
            av = loadA<MODE>(A, bm + lm, k0 + lk, K);
#pragma unroll
            for (int p = 0; p < WL; p++)
                wv[p] = *(const float4*)(W + (size_t)(bn + lm + p * BM) * Wstride + k0 + lk);
        }
#pragma unroll
        for (int kk = 0; kk < 16; kk++) {
            float4 a = *(const float4*)&As[kk][tm << 2];
            float4 w = *(const float4*)&Ws[kk][tn << 2];
            c[0][0] += a.x * w.x; c[0][1] += a.x * w.y; c[0][2] += a.x * w.z; c[0][3] += a.x * w.w;
            c[1][0] += a.y * w.x; c[1][1] += a.y * w.y; c[1][2] += a.y * w.z; c[1][3] += a.y * w.w;
            c[2][0] += a.z * w.x; c[2][1] += a.z * w.y; c[2][2] += a.z * w.z; c[2][3] += a.z * w.w;
            c[3][0] += a.w * w.x; c[3][1] += a.w * w.y; c[3][2] += a.w * w.z; c[3][3] += a.w * w.w;
        }
        if (k0 >= K) break;
    }

    const int col = bn + (tn << 2);
    float4 bi;
    if (!ACC) bi = *(const float4*)(bias + col);
#pragma unroll
    for (int i = 0; i < 4; i++) {
        int row = bm + (tm << 2) + i;
        float4 o;
        if (ACC) {
            float4 old = *(const float4*)(C + (size_t)row * Nd + col);
            o.x = c[i][0] + old.x; o.y = c[i][1] + old.y;
            o.z = c[i][2] + old.z; o.w = c[i][3] + old.w;
        } else {
            o.x = c[i][0] + bi.x; o.y = c[i][1] + bi.y;
            o.z = c[i][2] + bi.z; o.w = c[i][3] + bi.w;
        }
        *(float4*)(C + (size_t)row * Nd + col) = o;
    }
}

// ---------------- stage 1: eseg+histogram  ⊕  node scatter-mean --------------
__global__ __launch_bounds__(256) void k_eseg(const int* __restrict__ ei,
                                              const int* __restrict__ batch,
                                              const float* __restrict__ x,
                                              int E, int NB, int N) {
    if ((int)blockIdx.x >= NB) {
        __shared__ float red[8 * FD];
        __shared__ int   sb[2];
        const int b = blockIdx.x - NB;
        const int t = threadIdx.x;
        const int w = t >> 5, lane = t & 31;
        if (t == 0) {
            sb[0] = lowerb(batch, N, b);
            sb[1] = lowerb(batch, N, b + 1);
        }
        __syncthreads();
        const int ns = sb[0], ne = sb[1];
        float4 acn = make_float4(0.f, 0.f, 0.f, 0.f);
        int j = ns + w;
        for (; j + 24 < ne; j += 32) {
            float4 v0 = ((const float4*)(x + (size_t)(j + 0)  * FD))[lane];
            float4 v1 = ((const float4*)(x + (size_t)(j + 8)  * FD))[lane];
            float4 v2 = ((const float4*)(x + (size_t)(j + 16) * FD))[lane];
            float4 v3 = ((const float4*)(x + (size_t)(j + 24) * FD))[lane];
            acn.x += (v0.x + v1.x) + (v2.x + v3.x);
            acn.y += (v0.y + v1.y) + (v2.y + v3.y);
            acn.z += (v0.z + v1.z) + (v2.z + v3.z);
            acn.w += (v0.w + v1.w) + (v2.w + v3.w);
        }
        for (; j < ne; j += 8) {
            float4 v0 = ((const float4*)(x + (size_t)j * FD))[lane];
            acn.x += v0.x; acn.y += v0.y; acn.z += v0.z; acn.w += v0.w;
        }
        ((float4*)red)[w * 32 + lane] = acn;
        __syncthreads();
        if (t < FD) {
            float s2 = 0.f;
#pragma unroll
            for (int w2 = 0; w2 < 8; w2++) s2 += red[w2 * FD + t];
            int cnt = ne - ns;
            g_aggn[(size_t)b * FD + t] = s2 / (float)max(cnt, 1);
        }
        return;
    }

    __shared__ int sh[BB];
    for (int i = threadIdx.x; i < BB; i += blockDim.x) sh[i] = 0;
    __syncthreads();
    const int base = blockIdx.x * EPB;
#pragma unroll
    for (int r = 0; r < 8; r++) {
        int e = base + r * 256 + threadIdx.x;
        if (e < E) {
            int s = batch[ei[e]];
            g_eseg[e] = s;
            atomicAdd(&sh[s], 1);
        }
    }
    __syncthreads();
    for (int i = threadIdx.x; i < BB; i += blockDim.x)
        g_bhist[i * NB + blockIdx.x] = sh[i];
}

// ---------------- stage 2: per-segment scan over blocks + fused global scan --
__global__ __launch_bounds__(256) void k_colscan(int NB) {
    const int seg = blockIdx.x;
    int* col = g_bhist + (size_t)seg * NB;
    const int t = threadIdx.x, lane = t & 31, w = t >> 5;
    __shared__ int wsum[8];
    __shared__ int carry;
    __shared__ int lastblk;
    if (t == 0) carry = 0;
    __syncthreads();
    for (int base = 0; base < NB; base += 256) {
        int idx = base + t;
        int v = (idx < NB) ? col[idx] : 0;
        int inc = v;
#pragma unroll
        for (int o = 1; o < 32; o <<= 1) {
            int u2 = __shfl_up_sync(0xffffffffu, inc, o);
            if (lane >= o) inc += u2;
        }
        if (lane == 31) wsum[w] = inc;
        __syncthreads();
        int woff = 0;
        if (w > 0) {
#pragma unroll
            for (int i = 0; i < 7; i++) if (i < w) woff += wsum[i];
        }
        int excl = inc - v + woff + carry;
        if (idx < NB) col[idx] = excl;
        __syncthreads();
        if (t == 255) carry = excl + v;
        __syncthreads();
    }
    if (t == 0) {
        g_ehist[seg] = carry;
        __threadfence();
        int d = atomicAdd(&g_done, 1);
        lastblk = (d == gridDim.x - 1);
    }
    __syncthreads();
    if (!lastblk) return;

    // ----- fused stage 2b: last block scans the 1024 segment totals -----
    // 256 threads x 4 contiguous elements each.
    int v0 = g_ehist[t * 4 + 0];
    int v1 = g_ehist[t * 4 + 1];
    int v2 = g_ehist[t * 4 + 2];
    int v3 = g_ehist[t * 4 + 3];
    int s = ((v0 + v1) + (v2 + v3));
    int inc = s;
#pragma unroll
    for (int o = 1; o < 32; o <<= 1) {
        int u2 = __shfl_up_sync(0xffffffffu, inc, o);
        if (lane >= o) inc += u2;
    }
    if (lane == 31) wsum[w] = inc;
    __syncthreads();
    int woff = 0;
#pragma unroll
    for (int i = 0; i < 7; i++) if (i < w) woff += wsum[i];
    int excl = inc - s + woff;
    g_estart[t * 4 + 0] = excl;
    g_estart[t * 4 + 1] = excl + v0;
    g_estart[t * 4 + 2] = excl + v0 + v1;
    g_estart[t * 4 + 3] = excl + v0 + v1 + v2;
    if (t == 255) g_estart[BB] = excl + s;
    if (t == 0) g_done = 0;      // reset for next graph replay
}

// ---------------- stage 3: contention-free scatter (plain, low-reg) ----------
__global__ __launch_bounds__(256) void k_scatter2(int E, int NB) {
    __shared__ int cur[BB];
    const int blk = blockIdx.x;
    for (int sgi = threadIdx.x; sgi < BB; sgi += 256)
        cur[sgi] = g_estart[sgi] + g_bhist[(size_t)sgi * NB + blk];
    __syncthreads();
    const int base = blk * EPB;
#pragma unroll
    for (int r = 0; r < 8; r++) {
        int e = base + r * 256 + threadIdx.x;
        if (e < E) {
            int sgi = g_eseg[e];
            int p = atomicAdd(&cur[sgi], 1);
            g_perm[p] = e;
        }
    }
}

// ---------------- stage 4: [gh GEMM | pre-fc1 GEMM] first, then edge mean ----
__global__ __launch_bounds__(256) void k_agg(const float* __restrict__ ea,
                                             const float* __restrict__ h,
                                             const float* __restrict__ whh,
                                             const float* __restrict__ bhh,
                                             const float* __restrict__ u,
                                             const float* __restrict__ fc1w,
                                             const float* __restrict__ fc1b) {
    if (blockIdx.x < 192) {
        // ----- gh = h @ whh^T + bhh (independent of sort/agg) -----
        int g = blockIdx.x;                // 16 M-tiles x 12 N-tiles
        gemm_body<64, 0, false>(h, whh, bhh, g_gh, HS, HS, 3 * HS,
                                (g & 15) * 64, (g >> 4) * 64);
        return;
    }
    if (blockIdx.x < 256) {
        // ----- pre-fc1: t1 = u@Wu^T + aggn@Wn^T + b  (K=256) -----
        int g = blockIdx.x - 192;          // 16 M-tiles x 4 N-tiles
        gemm_body<64, 2, false>(u, fc1w, fc1b, g_t1, 2 * FD, INC, HS,
                                (g & 15) * 64, (g >> 4) * 64);
        return;
    }

    __shared__ float red[8 * FD];
    const int b = blockIdx.x - 256;
    const int t = threadIdx.x;
    const int w = t >> 5, lane = t & 31;

    const int es = g_estart[b], ee = g_estart[b + 1];
    float4 acc = make_float4(0.f, 0.f, 0.f, 0.f);
    int i = es + w;
    for (; i + 24 < ee; i += 32) {
        int e0 = g_perm[i];
        int e1 = g_perm[i + 8];
        int e2 = g_perm[i + 16];
        int e3 = g_perm[i + 24];
        float4 v0 = ((const float4*)(ea + (size_t)e0 * FD))[lane];
        float4 v1 = ((const float4*)(ea + (size_t)e1 * FD))[lane];
        float4 v2 = ((const float4*)(ea + (size_t)e2 * FD))[lane];
        float4 v3 = ((const float4*)(ea + (size_t)e3 * FD))[lane];
        acc.x += (v0.x + v1.x) + (v2.x + v3.x);
        acc.y += (v0.y + v1.y) + (v2.y + v3.y);
        acc.z += (v0.z + v1.z) + (v2.z + v3.z);
        acc.w += (v0.w + v1.w) + (v2.w + v3.w);
    }
    for (; i < ee; i += 8) {
        int e0 = g_perm[i];
        float4 v0 = ((const float4*)(ea + (size_t)e0 * FD))[lane];
        acc.x += v0.x; acc.y += v0.y; acc.z += v0.z; acc.w += v0.w;
    }
    ((float4*)red)[w * 32 + lane] = acc;
    __syncthreads();
    if (t < FD) {
        float s2 = 0.f;
#pragma unroll
        for (int w2 = 0; w2 < 8; w2++) s2 += red[w2 * FD + t];
        int cnt = ee - es;
        g_agge[(size_t)b * FD + t] = s2 / (float)max(cnt, 1);
    }
}

// ---------------- post-fc1: t1 += agge @ We^T  (K=128, BM=32) -----------------
__global__ __launch_bounds__(128) void k_fc1post(const float* __restrict__ fc1w) {
    gemm_body<32, 0, true>(g_agge, fc1w + 2 * FD, nullptr, g_t1, FD, INC, HS,
                           blockIdx.x * 32, blockIdx.y * 64);
}

// ---------------- MLP tail kernels -------------------------------------------
__global__ __launch_bounds__(256) void k_gru_gi(const float* __restrict__ wih,
                                                const float* __restrict__ bih) {
    gemm_body<64, 0, false>(g_zln, wih, bih, g_gi, HS, HS, 3 * HS,
                            blockIdx.x * 64, blockIdx.y * 64);
}

__global__ __launch_bounds__(128) void k_fc2(const float* __restrict__ hnew,
                                             const float* __restrict__ w,
                                             const float* __restrict__ b,
                                             float* __restrict__ out) {
    gemm_body<32, 0, false>(hnew, w, b, out, HS, HS, FD,
                            blockIdx.x * 32, blockIdx.y * 64);
}

// ---------------- LayerNorm + ReLU ------------------------------------------
__global__ __launch_bounds__(256) void k_ln(const float* __restrict__ g,
                                            const float* __restrict__ be) {
    const int b = blockIdx.x, t = threadIdx.x;
    float v = g_t1[(size_t)b * HS + t];
    float s = v, q = v * v;
#pragma unroll
    for (int o = 16; o; o >>= 1) {
        s += __shfl_down_sync(0xffffffffu, s, o);
        q += __shfl_down_sync(0xffffffffu, q, o);
    }
    __shared__ float ssum[8], ssq[8];
    __shared__ float smu, srv;
    if ((t & 31) == 0) { ssum[t >> 5] = s; ssq[t >> 5] = q; }
    __syncthreads();
    if (t == 0) {
        float S = 0.f, Q = 0.f;
#pragma unroll
        for (int i = 0; i < 8; i++) { S += ssum[i]; Q += ssq[i]; }
        float mu = S / (float)HS;
        float var = Q / (float)HS - mu * mu;
        smu = mu;
        srv = rsqrtf(var + 1e-5f);
    }
    __syncthreads();
    float o = (v - smu) * srv * g[t] + be[t];
    g_zln[(size_t)b * HS + t] = fmaxf(o, 0.f);
}

// ---------------- GRU gate combine (float4 vectorized) ------------------------
__global__ void k_gate(const float* __restrict__ h, float* __restrict__ hnew) {
    int idx = blockIdx.x * 256 + threadIdx.x;   // BB*HS/4 items
    int b = idx >> 6;
    int j = (idx & 63) * 4;
    const float* gi = g_gi + (size_t)b * 3 * HS;
    const float* gh = g_gh + (size_t)b * 3 * HS;
    float4 gir = *(const float4*)(gi + j);
    float4 giz = *(const float4*)(gi + HS + j);
    float4 gin = *(const float4*)(gi + 2 * HS + j);
    float4 ghr = *(const float4*)(gh + j);
    float4 ghz = *(const float4*)(gh + HS + j);
    float4 ghn = *(const float4*)(gh + 2 * HS + j);
    float4 hv  = *(const float4*)(h + (size_t)b * HS + j);
    float4 o;
#define GATE1(cc) { \
    float r  = 1.f / (1.f + expf(-(gir.cc + ghr.cc))); \
    float zg = 1.f / (1.f + expf(-(giz.cc + ghz.cc))); \
    float n  = tanhf(gin.cc + r * ghn.cc); \
    o.cc = (1.f - zg) * n + zg * hv.cc; }
    GATE1(x) GATE1(y) GATE1(z) GATE1(w)
#undef GATE1
    *(float4*)(hnew + (size_t)b * HS + j) = o;
}

// ---------------- launch ----------------------------------------------------
extern "C" void kernel_launch(void* const* d_in, const int* in_sizes, int n_in,
                              void* d_out, int out_size) {
    const float* x     = (const float*)d_in[0];
    const int*   ei    = (const int*)d_in[1];
    const float* ea    = (const float*)d_in[2];
    const float* h     = (const float*)d_in[3];
    const float* u     = (const float*)d_in[4];
    const int*   batch = (const int*)d_in[5];
    const float* fc1w  = (const float*)d_in[6];
    const float* fc1b  = (const float*)d_in[7];
    const float* lng   = (const float*)d_in[8];
    const float* lnb   = (const float*)d_in[9];
    const float* wih   = (const float*)d_in[10];
    const float* whh   = (const float*)d_in[11];
    const float* bih   = (const float*)d_in[12];
    const float* bhh   = (const float*)d_in[13];
    const float* fc2w  = (const float*)d_in[14];
    const float* fc2b  = (const float*)d_in[15];

    const int N = in_sizes[0] / FD;
    const int E = in_sizes[2] / FD;
    const int NB = (E + EPB - 1) / EPB;

    float* out  = (float*)d_out;           // [BB, FD]
    float* hnew = out + (size_t)BB * FD;   // [BB, HS]

    // eseg/hist ⊕ node-mean
    k_eseg<<<NB + BB, 256>>>(ei, batch, x, E, NB, N);
    // per-segment scan over blocks + fused 1024-total scan (last block)
    k_colscan<<<BB, 256>>>(NB);
    k_scatter2<<<NB, 256>>>(E, NB);
    // gh GEMM + pre-fc1 GEMM first (finish inside agg's stream), then edge-mean
    k_agg<<<256 + BB, 256>>>(ea, h, whh, bhh, u, fc1w, fc1b);

    k_fc1post<<<dim3(BB / 32, HS / 64), 128>>>(fc1w);
    k_ln<<<BB, HS>>>(lng, lnb);
    k_gru_gi<<<dim3(BB / 64, (3 * HS) / 64), 256>>>(wih, bih);
    k_gate<<<(BB * HS / 4) / 256, 256>>>(h, hnew);
    k_fc2<<<dim3(BB / 32, FD / 64), 128>>>(hnew, fc2w, fc2b, out);
}